// round 7
// baseline (speedup 1.0000x reference)
#include <cuda_runtime.h>

#define C   32
#define HF  96
#define WF  192
#define DD  192
#define HOUT 384
#define WOUT 768
#define ND  48
#define CHW (HF*WF)
#define COST_ELEMS (DD*HF*WF)
#define TP  (WF + 16)          // padded t row: 16 zero floats before index 0

// ---- packed f32x2 helpers (sm_103a) ----------------------------------------
__device__ __forceinline__ unsigned long long pack2(float lo, float hi) {
    unsigned long long r;
    asm("mov.b64 %0, {%1, %2};" : "=l"(r) : "f"(lo), "f"(hi));
    return r;
}
__device__ __forceinline__ void fma2(unsigned long long& acc,
                                     unsigned long long a, unsigned long long b) {
    asm("fma.rn.f32x2 %0, %1, %2, %0;" : "+l"(acc) : "l"(a), "l"(b));
}
__device__ __forceinline__ float2 unpack2(unsigned long long v) {
    float lo, hi;
    asm("mov.b64 {%0, %1}, %2;" : "=f"(lo), "=f"(hi) : "l"(v));
    return make_float2(lo, hi);
}

// ---------------------------------------------------------------------------
// Kernel 1: normalized cosine cost volume. ONE WAVE: grid (48 h-pairs, 3),
// 384 threads, ~100KB dynamic smem. Each thread computes one 8w x 8d tile:
// per c-iter 6 LDS.128 feed 64 FMAs (32 fma.rn.f32x2) -> crossbar bytes/FMA
// drop 25% vs 4w tiles, and the crossbar is the binding pipe.
// Zero-padded t rows keep one branch-free code path across the triangle.
// cost[d,h,w] = sum_c rn[c,w]*tn[c,w-d], exactly 0 for w<d.
// ---------------------------------------------------------------------------
__global__ __launch_bounds__(384, 1) void cost_kernel(
    const float* __restrict__ ref, const float* __restrict__ tgt,
    float* __restrict__ out)
{
    extern __shared__ float smbuf[];
    float (*r)[C][WF] = reinterpret_cast<float (*)[C][WF]>(smbuf);
    float (*t)[C][TP] = reinterpret_cast<float (*)[C][TP]>(smbuf + 2*C*WF);

    const int hp  = blockIdx.x;          // h-pair 0..47
    const int by  = blockIdx.y;          // 0..2
    const int tid = threadIdx.x;         // 0..383
    const int hrow0 = hp * 2;

    // zero the 2*C*16 pad floats (= 256 float4 lanes)
    if (tid < 2*C*4) {
        int row = tid / (C*4);
        int c   = (tid / 4) % C;
        int q   = tid % 4;
        *reinterpret_cast<float4*>(&t[row][c][q*4]) = make_float4(0.f,0.f,0.f,0.f);
    }

    // vectorized loads: 3072 float4 per tensor (2 rows x 32 c x 48 quads)
    #pragma unroll
    for (int j = 0; j < 8; j++) {
        int k   = tid + j*384;           // 0..3071
        int c   = k / 48;                // row*32 + channel
        int kk  = k % 48;
        int row = c / C;
        int cc  = c % C;
        *reinterpret_cast<float4*>(&r[row][cc][kk*4]) =
            *reinterpret_cast<const float4*>(ref + cc*CHW + (hrow0+row)*WF + kk*4);
        *reinterpret_cast<float4*>(&t[row][cc][16 + kk*4]) =
            *reinterpret_cast<const float4*>(tgt + cc*CHW + (hrow0+row)*WF + kk*4);
    }
    __syncthreads();

    // per-pixel channel normalization: 384 columns == blockDim
    {
        int row = tid / WF;
        int w   = tid % WF;
        float sr = 0.f, st = 0.f;
        #pragma unroll
        for (int c = 0; c < C; c++) {
            float a = r[row][c][w];      sr = fmaf(a, a, sr);
            float b = t[row][c][16 + w]; st = fmaf(b, b, st);
        }
        float ir  = rsqrtf(sr + 1e-12f);
        float itv = rsqrtf(st + 1e-12f);
        #pragma unroll
        for (int c = 0; c < C; c++) { r[row][c][w] *= ir; t[row][c][16 + w] *= itv; }
    }
    __syncthreads();

    // one 8w x 8d tile per thread: 2h x 8dq x 24w = 384 tiles
    const int hr = tid / 192;
    const int tm = tid % 192;
    const int w8 = tm % 24;
    const int dq = tm / 24;              // 0..7
    const int w0 = w8 * 8;
    const int d0 = 8 * (3*dq + by);      // interleaved d-oct (triangle balance)
    const int h  = hrow0 + hr;

    // acc[g][i]: packed pair (w0+2g, w0+2g+1) at d = d0+i
    unsigned long long acc[4][8];
    #pragma unroll
    for (int g = 0; g < 4; g++)
        #pragma unroll
        for (int i = 0; i < 8; i++) acc[g][i] = 0ULL;

    // padded window base: e[j] = t[pb+j], b(w,d) = e[(w-w0)-(d-d0)+8]
    const int pb = 16 + w0 - d0 - 8;     // multiple of 4... (w0,d0 mult of 8)

    if (pb >= 0) {                       // else whole tile is w<d -> zeros
        #pragma unroll 4
        for (int c = 0; c < C; c++) {
            float4 a0 = *reinterpret_cast<const float4*>(&r[hr][c][w0]);
            float4 a1 = *reinterpret_cast<const float4*>(&r[hr][c][w0+4]);
            float4 v0 = *reinterpret_cast<const float4*>(&t[hr][c][pb]);
            float4 v1 = *reinterpret_cast<const float4*>(&t[hr][c][pb + 4]);
            float4 v2 = *reinterpret_cast<const float4*>(&t[hr][c][pb + 8]);
            float4 v3 = *reinterpret_cast<const float4*>(&t[hr][c][pb + 12]);
            float e[16] = {v0.x, v0.y, v0.z, v0.w,  v1.x, v1.y, v1.z, v1.w,
                           v2.x, v2.y, v2.z, v2.w,  v3.x, v3.y, v3.z, v3.w};
            unsigned long long A[4] = { pack2(a0.x, a0.y), pack2(a0.z, a0.w),
                                        pack2(a1.x, a1.y), pack2(a1.z, a1.w) };
            unsigned long long P[15];
            #pragma unroll
            for (int j = 1; j <= 14; j++) P[j] = pack2(e[j], e[j+1]);
            // acc[g][i] += A[g] * P[2g - i + 8]
            #pragma unroll
            for (int g = 0; g < 4; g++) {
                #pragma unroll
                for (int i = 0; i < 8; i++)
                    fma2(acc[g][i], A[g], P[2*g - i + 8]);
            }
        }
    }

    #pragma unroll
    for (int i = 0; i < 8; i++) {
        float2 p0 = unpack2(acc[0][i]);
        float2 p1 = unpack2(acc[1][i]);
        float2 p2 = unpack2(acc[2][i]);
        float2 p3 = unpack2(acc[3][i]);
        float* dst = &out[((d0 + i)*HF + h)*WF + w0];
        *reinterpret_cast<float4*>(dst)     = make_float4(p0.x, p0.y, p1.x, p1.y);
        *reinterpret_cast<float4*>(dst + 4) = make_float4(p2.x, p2.y, p3.x, p3.y);
    }
}

// ---------------------------------------------------------------------------
// Kernel 2: fused trilinear upsample (jax half-pixel == clamped lerp) +
// argmax over 192 d-samples + clamp(.,1). Direct 4-corner chunked streaming
// with explicit buffer alternation; x8-scaled candidate scan (exact, order-
// preserving): cand(e) = 7*s[e] + max(s[e-1], s[e+1]); exact-sample
// candidates 8*s[0] (k=0) and 8*s[47] (k=190). First-occurrence ties kept.
// ---------------------------------------------------------------------------
#define SSTR 52

__device__ __forceinline__ float bilin1(const float* __restrict__ c00,
                                        const float* __restrict__ c01,
                                        const float* __restrict__ c10,
                                        const float* __restrict__ c11,
                                        int d, float fw, float fh)
{
    float t0 = fmaf(fw, c01[d] - c00[d], c00[d]);
    float t1 = fmaf(fw, c11[d] - c10[d], c10[d]);
    return fmaf(fh, t1 - t0, t0);
}

__device__ __forceinline__ void chunk8(const float* __restrict__ c00,
                                       const float* __restrict__ c01,
                                       const float* __restrict__ c10,
                                       const float* __restrict__ c11,
                                       int dbase, float fw, float fh,
                                       float* __restrict__ s)
{
    #pragma unroll
    for (int half = 0; half < 2; half++) {
        float4 v00 = *reinterpret_cast<const float4*>(c00 + dbase + half*4);
        float4 v01 = *reinterpret_cast<const float4*>(c01 + dbase + half*4);
        float4 v10 = *reinterpret_cast<const float4*>(c10 + dbase + half*4);
        float4 v11 = *reinterpret_cast<const float4*>(c11 + dbase + half*4);
        float t0, t1;
        t0 = fmaf(fw, v01.x - v00.x, v00.x);
        t1 = fmaf(fw, v11.x - v10.x, v10.x);
        s[half*4+0] = fmaf(fh, t1 - t0, t0);
        t0 = fmaf(fw, v01.y - v00.y, v00.y);
        t1 = fmaf(fw, v11.y - v10.y, v10.y);
        s[half*4+1] = fmaf(fh, t1 - t0, t0);
        t0 = fmaf(fw, v01.z - v00.z, v00.z);
        t1 = fmaf(fw, v11.z - v10.z, v10.z);
        s[half*4+2] = fmaf(fh, t1 - t0, t0);
        t0 = fmaf(fw, v01.w - v00.w, v00.w);
        t1 = fmaf(fw, v11.w - v10.w, v10.w);
        s[half*4+3] = fmaf(fh, t1 - t0, t0);
    }
}

__device__ __forceinline__ void scan_head(const float* __restrict__ s,
                                          float& best, int& bestE)
{
    #pragma unroll
    for (int e = 0; e < 7; e++) {
        float nb = (e == 0) ? s[1] : fmaxf(s[e-1], s[e+1]);
        float cand = fmaf(7.0f, s[e], nb);
        if (cand > best) { best = cand; bestE = e; }
    }
}

__device__ __forceinline__ void scan_mid(const float* __restrict__ p,
                                         const float* __restrict__ c,
                                         int qb, float& best, int& bestE)
{
    {   float nb = fmaxf(p[6], c[0]);
        float cand = fmaf(7.0f, p[7], nb);
        if (cand > best) { best = cand; bestE = qb - 1; } }
    {   float nb = fmaxf(p[7], c[1]);
        float cand = fmaf(7.0f, c[0], nb);
        if (cand > best) { best = cand; bestE = qb; } }
    #pragma unroll
    for (int j = 1; j < 7; j++) {
        float nb = fmaxf(c[j-1], c[j+1]);
        float cand = fmaf(7.0f, c[j], nb);
        if (cand > best) { best = cand; bestE = qb + j; }
    }
}

__global__ __launch_bounds__(256) void pred_kernel(
    const float* __restrict__ cost, float* __restrict__ pred)
{
    __shared__ float sc[4][10][SSTR];  // [h-row][w-col][d], padded stride
    const int tx = threadIdx.x, ty = threadIdx.y;
    const int tid = ty*32 + tx;
    const int hb = 2*(int)blockIdx.y - 1;
    const int wb = 8*(int)blockIdx.x - 1;

    #pragma unroll
    for (int it = 0; it < 8; it++) {
        int i = tid + it * 256;
        if (i < 4*10*ND) {
            int wc = i % 10;
            int hr = (i / 10) % 4;
            int d  = i / 40;
            int hh = min(max(hb + hr, 0), HF - 1);
            int ww = min(max(wb + wc, 0), WF - 1);
            sc[hr][wc][d] = cost[(d*HF + hh)*WF + ww];
        }
    }
    __syncthreads();

    const int wo = blockIdx.x*32 + tx;
    const int ho = blockIdx.y*8 + ty;

    float xh = fminf(fmaxf(0.25f*(float)ho - 0.375f, 0.f), (float)(HF - 1));
    int   h0 = min((int)xh, HF - 2);
    float fh = xh - (float)h0;
    float xw = fminf(fmaxf(0.25f*(float)wo - 0.375f, 0.f), (float)(WF - 1));
    int   w0 = min((int)xw, WF - 2);
    float fw = xw - (float)w0;

    const int lh = h0 - hb;
    const int lw = w0 - wb;
    const float* c00 = &sc[lh][lw][0];
    const float* c01 = &sc[lh][lw+1][0];
    const float* c10 = &sc[lh+1][lw][0];
    const float* c11 = &sc[lh+1][lw+1][0];

    float sA[8], sB[8];
    float best;
    int bestE = -1;                      // -1 => k = 0

    chunk8(c00, c01, c10, c11, 0, fw, fh, sA);
    best = 8.0f * sA[0];                 // exact sample s[0] (scaled)
    scan_head(sA, best, bestE);

    chunk8(c00, c01, c10, c11,  8, fw, fh, sB); scan_mid(sA, sB,  8, best, bestE);
    chunk8(c00, c01, c10, c11, 16, fw, fh, sA); scan_mid(sB, sA, 16, best, bestE);
    chunk8(c00, c01, c10, c11, 24, fw, fh, sB); scan_mid(sA, sB, 24, best, bestE);
    chunk8(c00, c01, c10, c11, 32, fw, fh, sA); scan_mid(sB, sA, 32, best, bestE);
    chunk8(c00, c01, c10, c11, 40, fw, fh, sB); scan_mid(sA, sB, 40, best, bestE);

    {   // e = 47
        float nb = sB[6];
        float cand = fmaf(7.0f, sB[7], nb);
        if (cand > best) { best = cand; bestE = 47; }
    }
    float s47 = sB[7];

    int k;
    if (8.0f * s47 > best) {
        k = 4*(ND-1) + 2;                   // 190: exact sample s[47]
    } else if (bestE < 0) {
        k = 0;
    } else {
        float smL = -3.0e38f, smR = -3.0e38f;
        if (bestE > 0)      smL = bilin1(c00, c01, c10, c11, bestE - 1, fw, fh);
        if (bestE < ND - 1) smR = bilin1(c00, c01, c10, c11, bestE + 1, fw, fh);
        k = 4*bestE + 1 + ((smR > smL) ? 1 : 0);   // tie -> left (smaller k)
    }
    k = max(k, 1);
    pred[ho*WOUT + wo] = (float)k;
}

// ---------------------------------------------------------------------------
extern "C" void kernel_launch(void* const* d_in, const int* in_sizes, int n_in,
                              void* d_out, int out_size)
{
    const float* left  = (const float*)d_in[0];
    const float* right = (const float*)d_in[1];
    float* out = (float*)d_out;

    const int smem_bytes = (2*C*WF + 2*C*TP) * (int)sizeof(float);  // 100 KB
    cudaFuncSetAttribute(cost_kernel,
                         cudaFuncAttributeMaxDynamicSharedMemorySize, smem_bytes);

    dim3 g1(HF/2, 3), b1(384);
    cost_kernel<<<g1, b1, smem_bytes>>>(left, right, out);

    dim3 g2(WOUT/32, HOUT/8), b2(32, 8);
    pred_kernel<<<g2, b2>>>(out, out + COST_ELEMS);
}

// round 8
// speedup vs baseline: 1.0817x; 1.0817x over previous
#include <cuda_runtime.h>

#define C   32
#define HF  96
#define WF  192
#define DD  192
#define HOUT 384
#define WOUT 768
#define ND  48
#define CHW (HF*WF)
#define COST_ELEMS (DD*HF*WF)
#define TP  (WF + 16)          // padded t/it rows: 16 zero floats before idx 0

// ---- packed f32x2 helpers (sm_103a) ----------------------------------------
__device__ __forceinline__ unsigned long long pack2(float lo, float hi) {
    unsigned long long r;
    asm("mov.b64 %0, {%1, %2};" : "=l"(r) : "f"(lo), "f"(hi));
    return r;
}
__device__ __forceinline__ void fma2(unsigned long long& acc,
                                     unsigned long long a, unsigned long long b) {
    asm("fma.rn.f32x2 %0, %1, %2, %0;" : "+l"(acc) : "l"(a), "l"(b));
}
__device__ __forceinline__ unsigned long long mul2(unsigned long long a,
                                                   unsigned long long b) {
    unsigned long long r;
    asm("mul.rn.f32x2 %0, %1, %2;" : "=l"(r) : "l"(a), "l"(b));
    return r;
}
__device__ __forceinline__ float2 unpack2(unsigned long long v) {
    float lo, hi;
    asm("mov.b64 {%0, %1}, %2;" : "=f"(lo), "=f"(hi) : "l"(v));
    return make_float2(lo, hi);
}

// ---------------------------------------------------------------------------
// Kernel 1: cosine cost volume, normalization deferred to store time.
// ONE WAVE: grid (48 h-pairs, 3), 768 threads, ~106KB dynamic smem.
// smem holds UNNORMALIZED r,t rows; only per-pixel inverse norms ir/it are
// computed (all 24 warps, split-c partials). Main loop: one 4w x 8d tile per
// thread, LDS.128 operands, fma.rn.f32x2 accumulation. Store applies
// out = acc * ir[w] * it[w-d]; zero-padded t AND it keep exact zeros for w<d.
// ---------------------------------------------------------------------------
__global__ __launch_bounds__(768, 1) void cost_kernel(
    const float* __restrict__ ref, const float* __restrict__ tgt,
    float* __restrict__ out)
{
    extern __shared__ float smbuf[];
    float (*r)[C][WF]  = reinterpret_cast<float (*)[C][WF]>(smbuf);
    float (*t)[C][TP]  = reinterpret_cast<float (*)[C][TP]>(smbuf + 2*C*WF);
    float* part_r      = smbuf + 2*C*WF + 2*C*TP;          // [384]
    float* part_t      = part_r + 2*WF;                    // [384]
    float (*ir)[WF]    = reinterpret_cast<float (*)[WF]>(part_t + 2*WF);
    float (*itp)[TP]   = reinterpret_cast<float (*)[TP]>(
                             reinterpret_cast<float*>(ir) + 2*WF);

    const int hp  = blockIdx.x;          // h-pair 0..47
    const int by  = blockIdx.y;          // 0..2
    const int tid = threadIdx.x;         // 0..767
    const int hrow0 = hp * 2;

    // zero t pad (2*32*16 floats = 256 float4) and itp pad (32 floats = 8 f4)
    if (tid < 256) {
        int row = tid / 128;
        int c   = (tid / 4) % C;
        int q   = tid % 4;
        *reinterpret_cast<float4*>(&t[row][c][q*4]) = make_float4(0.f,0.f,0.f,0.f);
    } else if (tid < 264) {
        int idx = tid - 256;
        int row = idx / 4;
        int q   = idx % 4;
        *reinterpret_cast<float4*>(&itp[row][q*4]) = make_float4(0.f,0.f,0.f,0.f);
    }

    // vectorized loads: 3072 float4 per tensor (2 rows x 32 c x 48 quads)
    #pragma unroll
    for (int j = 0; j < 4; j++) {
        int k   = tid + j*768;
        int c   = k / 48;                // row*32 + channel
        int kk  = k % 48;
        int row = c / C;
        int cc  = c % C;
        *reinterpret_cast<float4*>(&r[row][cc][kk*4]) =
            *reinterpret_cast<const float4*>(ref + cc*CHW + (hrow0+row)*WF + kk*4);
        *reinterpret_cast<float4*>(&t[row][cc][16 + kk*4]) =
            *reinterpret_cast<const float4*>(tgt + cc*CHW + (hrow0+row)*WF + kk*4);
    }
    __syncthreads();

    // inverse norms: 384 columns x 2 half-c partials (all 24 warps active)
    {
        int col  = tid % 384;            // row*192 + w
        int half = tid / 384;
        int row  = col / WF;
        int w    = col % WF;
        float sr = 0.f, st = 0.f;
        int cbase = half * 16;
        #pragma unroll
        for (int c = 0; c < 16; c++) {
            float a = r[row][cbase + c][w];      sr = fmaf(a, a, sr);
            float b = t[row][cbase + c][16 + w]; st = fmaf(b, b, st);
        }
        if (half) { part_r[col] = sr; part_t[col] = st; }
        __syncthreads();
        if (!half) {
            ir[row][w]       = rsqrtf(sr + part_r[col] + 1e-12f);
            itp[row][16 + w] = rsqrtf(st + part_t[col] + 1e-12f);
        }
    }
    __syncthreads();

    // one 4w x 8d tile per thread
    const int hr = (tid >= 384) ? 1 : 0;
    const int tm = tid - hr*384;
    const int wq = tm % 48;
    const int dq = tm / 48;
    const int w0 = wq * 4;
    const int d0 = 8 * (3*dq + by);      // interleaved d-oct (triangle balance)
    const int h  = hrow0 + hr;

    unsigned long long axy0[8], azw0[8]; // (x,y) / (z,w) packed accs per i
    #pragma unroll
    for (int i = 0; i < 8; i++) { axy0[i] = 0ULL; azw0[i] = 0ULL; }

    const int pb = 16 + w0 - d0 - 8;     // padded window base (mult of 4)

    if (w0 - d0 >= 0) {
        for (int c = 0; c < C; c++) {
            float4 a  = *reinterpret_cast<const float4*>(&r[hr][c][w0]);
            float4 v0 = *reinterpret_cast<const float4*>(&t[hr][c][pb]);
            float4 v1 = *reinterpret_cast<const float4*>(&t[hr][c][pb + 4]);
            float4 v2 = *reinterpret_cast<const float4*>(&t[hr][c][pb + 8]);
            float e[12] = {v0.x, v0.y, v0.z, v0.w,
                           v1.x, v1.y, v1.z, v1.w,
                           v2.x, v2.y, v2.z, v2.w};
            unsigned long long pxy = pack2(a.x, a.y);
            unsigned long long pzw = pack2(a.z, a.w);
            // axy0[i] += (a.x,a.y)*(e[8-i],e[9-i]); azw0[i] += (a.z,a.w)*(e[10-i],e[11-i])
            #pragma unroll
            for (int j = 1; j <= 10; j++) {
                unsigned long long P = pack2(e[j], e[j+1]);
                if (j <= 8) fma2(axy0[8 - j], pxy, P);
                if (j >= 3) fma2(azw0[10 - j], pzw, P);
            }
        }
        // store with deferred normalization: out = acc * ir[w] * it[w-d]
        float4 irq = *reinterpret_cast<const float4*>(&ir[hr][w0]);
        float4 s0 = *reinterpret_cast<const float4*>(&itp[hr][pb]);
        float4 s1 = *reinterpret_cast<const float4*>(&itp[hr][pb + 4]);
        float4 s2 = *reinterpret_cast<const float4*>(&itp[hr][pb + 8]);
        float e[12] = {s0.x, s0.y, s0.z, s0.w,
                       s1.x, s1.y, s1.z, s1.w,
                       s2.x, s2.y, s2.z, s2.w};
        #pragma unroll
        for (int i = 0; i < 8; i++) {
            float2 xy = unpack2(axy0[i]);
            float2 zw = unpack2(azw0[i]);
            float4 o;
            o.x = xy.x * irq.x * e[8  - i];
            o.y = xy.y * irq.y * e[9  - i];
            o.z = zw.x * irq.z * e[10 - i];
            o.w = zw.y * irq.w * e[11 - i];
            *reinterpret_cast<float4*>(&out[((d0 + i)*HF + h)*WF + w0]) = o;
        }
    } else {
        float4 z = make_float4(0.f, 0.f, 0.f, 0.f);
        #pragma unroll
        for (int i = 0; i < 8; i++)
            *reinterpret_cast<float4*>(&out[((d0 + i)*HF + h)*WF + w0]) = z;
    }
}

// ---------------------------------------------------------------------------
// Kernel 2: fused trilinear upsample + argmax + clamp(.,1).
// Weight-form bilinear with packed f32x2: s = w00*v00+w01*v01+w10*v10+w11*v11
// (2 packed ops per d-pair). x8-scaled candidate scan (exact, order-
// preserving): cand(e) = 7*s[e] + max(s[e-1], s[e+1]); exact-sample
// candidates 8*s[0] (k=0) and 8*s[47] (k=190). First-occurrence ties kept.
// ---------------------------------------------------------------------------
#define SSTR 52

__device__ __forceinline__ void chunk8w(const float* __restrict__ c00,
                                        const float* __restrict__ c01,
                                        const float* __restrict__ c10,
                                        const float* __restrict__ c11,
                                        int dbase,
                                        unsigned long long W00,
                                        unsigned long long W01,
                                        unsigned long long W10,
                                        unsigned long long W11,
                                        float* __restrict__ s)
{
    #pragma unroll
    for (int half = 0; half < 2; half++) {
        ulonglong2 u00 = *reinterpret_cast<const ulonglong2*>(c00 + dbase + half*4);
        ulonglong2 u01 = *reinterpret_cast<const ulonglong2*>(c01 + dbase + half*4);
        ulonglong2 u10 = *reinterpret_cast<const ulonglong2*>(c10 + dbase + half*4);
        ulonglong2 u11 = *reinterpret_cast<const ulonglong2*>(c11 + dbase + half*4);
        unsigned long long p0 = mul2(u00.x, W00);
        fma2(p0, u01.x, W01); fma2(p0, u10.x, W10); fma2(p0, u11.x, W11);
        unsigned long long p1 = mul2(u00.y, W00);
        fma2(p1, u01.y, W01); fma2(p1, u10.y, W10); fma2(p1, u11.y, W11);
        float2 a = unpack2(p0);
        float2 b = unpack2(p1);
        s[half*4+0] = a.x; s[half*4+1] = a.y;
        s[half*4+2] = b.x; s[half*4+3] = b.y;
    }
}

__device__ __forceinline__ float wlerp1(const float* __restrict__ c00,
                                        const float* __restrict__ c01,
                                        const float* __restrict__ c10,
                                        const float* __restrict__ c11,
                                        int d, float w00, float w01,
                                        float w10, float w11)
{
    float s = c00[d] * w00;
    s = fmaf(c01[d], w01, s);
    s = fmaf(c10[d], w10, s);
    s = fmaf(c11[d], w11, s);
    return s;
}

__device__ __forceinline__ void scan_head(const float* __restrict__ s,
                                          float& best, int& bestE)
{
    #pragma unroll
    for (int e = 0; e < 7; e++) {
        float nb = (e == 0) ? s[1] : fmaxf(s[e-1], s[e+1]);
        float cand = fmaf(7.0f, s[e], nb);
        if (cand > best) { best = cand; bestE = e; }
    }
}

__device__ __forceinline__ void scan_mid(const float* __restrict__ p,
                                         const float* __restrict__ c,
                                         int qb, float& best, int& bestE)
{
    {   float nb = fmaxf(p[6], c[0]);
        float cand = fmaf(7.0f, p[7], nb);
        if (cand > best) { best = cand; bestE = qb - 1; } }
    {   float nb = fmaxf(p[7], c[1]);
        float cand = fmaf(7.0f, c[0], nb);
        if (cand > best) { best = cand; bestE = qb; } }
    #pragma unroll
    for (int j = 1; j < 7; j++) {
        float nb = fmaxf(c[j-1], c[j+1]);
        float cand = fmaf(7.0f, c[j], nb);
        if (cand > best) { best = cand; bestE = qb + j; }
    }
}

__global__ __launch_bounds__(256) void pred_kernel(
    const float* __restrict__ cost, float* __restrict__ pred)
{
    __shared__ float sc[4][10][SSTR];  // [h-row][w-col][d], padded stride
    const int tx = threadIdx.x, ty = threadIdx.y;
    const int tid = ty*32 + tx;
    const int hb = 2*(int)blockIdx.y - 1;
    const int wb = 8*(int)blockIdx.x - 1;

    #pragma unroll
    for (int it = 0; it < 8; it++) {
        int i = tid + it * 256;
        if (i < 4*10*ND) {
            int wc = i % 10;
            int hr = (i / 10) % 4;
            int d  = i / 40;
            int hh = min(max(hb + hr, 0), HF - 1);
            int ww = min(max(wb + wc, 0), WF - 1);
            sc[hr][wc][d] = cost[(d*HF + hh)*WF + ww];
        }
    }
    __syncthreads();

    const int wo = blockIdx.x*32 + tx;
    const int ho = blockIdx.y*8 + ty;

    float xh = fminf(fmaxf(0.25f*(float)ho - 0.375f, 0.f), (float)(HF - 1));
    int   h0 = min((int)xh, HF - 2);
    float fh = xh - (float)h0;
    float xw = fminf(fmaxf(0.25f*(float)wo - 0.375f, 0.f), (float)(WF - 1));
    int   w0 = min((int)xw, WF - 2);
    float fw = xw - (float)w0;

    const int lh = h0 - hb;
    const int lw = w0 - wb;
    const float* c00 = &sc[lh][lw][0];
    const float* c01 = &sc[lh][lw+1][0];
    const float* c10 = &sc[lh+1][lw][0];
    const float* c11 = &sc[lh+1][lw+1][0];

    const float gw = 1.0f - fw, gh = 1.0f - fh;
    const float w00s = gw*gh, w01s = fw*gh, w10s = gw*fh, w11s = fw*fh;
    const unsigned long long W00 = pack2(w00s, w00s);
    const unsigned long long W01 = pack2(w01s, w01s);
    const unsigned long long W10 = pack2(w10s, w10s);
    const unsigned long long W11 = pack2(w11s, w11s);

    float sA[8], sB[8];
    float best;
    int bestE = -1;                      // -1 => k = 0

    chunk8w(c00, c01, c10, c11, 0, W00, W01, W10, W11, sA);
    best = 8.0f * sA[0];                 // exact sample s[0] (scaled)
    scan_head(sA, best, bestE);

    chunk8w(c00, c01, c10, c11,  8, W00, W01, W10, W11, sB);
    scan_mid(sA, sB,  8, best, bestE);
    chunk8w(c00, c01, c10, c11, 16, W00, W01, W10, W11, sA);
    scan_mid(sB, sA, 16, best, bestE);
    chunk8w(c00, c01, c10, c11, 24, W00, W01, W10, W11, sB);
    scan_mid(sA, sB, 24, best, bestE);
    chunk8w(c00, c01, c10, c11, 32, W00, W01, W10, W11, sA);
    scan_mid(sB, sA, 32, best, bestE);
    chunk8w(c00, c01, c10, c11, 40, W00, W01, W10, W11, sB);
    scan_mid(sA, sB, 40, best, bestE);

    {   // e = 47
        float nb = sB[6];
        float cand = fmaf(7.0f, sB[7], nb);
        if (cand > best) { best = cand; bestE = 47; }
    }
    float s47 = sB[7];

    int k;
    if (8.0f * s47 > best) {
        k = 4*(ND-1) + 2;                   // 190: exact sample s[47]
    } else if (bestE < 0) {
        k = 0;
    } else {
        float smL = -3.0e38f, smR = -3.0e38f;
        if (bestE > 0)
            smL = wlerp1(c00, c01, c10, c11, bestE - 1, w00s, w01s, w10s, w11s);
        if (bestE < ND - 1)
            smR = wlerp1(c00, c01, c10, c11, bestE + 1, w00s, w01s, w10s, w11s);
        k = 4*bestE + 1 + ((smR > smL) ? 1 : 0);   // tie -> left (smaller k)
    }
    k = max(k, 1);
    pred[ho*WOUT + wo] = (float)k;
}

// ---------------------------------------------------------------------------
extern "C" void kernel_launch(void* const* d_in, const int* in_sizes, int n_in,
                              void* d_out, int out_size)
{
    const float* left  = (const float*)d_in[0];
    const float* right = (const float*)d_in[1];
    float* out = (float*)d_out;

    const int smem_bytes =
        (2*C*WF + 2*C*TP + 2*WF + 2*WF + 2*WF + 2*TP) * (int)sizeof(float);
    cudaFuncSetAttribute(cost_kernel,
                         cudaFuncAttributeMaxDynamicSharedMemorySize, smem_bytes);

    dim3 g1(HF/2, 3), b1(768);
    cost_kernel<<<g1, b1, smem_bytes>>>(left, right, out);

    dim3 g2(WOUT/32, HOUT/8), b2(32, 8);
    pred_kernel<<<g2, b2>>>(out, out + COST_ELEMS);
}